// round 1
// baseline (speedup 1.0000x reference)
#include <cuda_runtime.h>

#define CC   2
#define HH   200
#define WW   200
#define NN   200
#define HWN  (HH*WW*NN)
#define N4   (NN/4)                     // 50 float4 groups per (h,w)
#define TOTAL_THREADS (HH*WW*N4)        // 2,000,000

// Per-n precomputed ROI params:
//   g_prep[2*n]   = (x1, y1, x2, y2)
//   g_prep[2*n+1] = (2/cw, 2/ch, -, -)
__device__ float4 g_prep[2 * NN];

__global__ void prep_kernel(const float* __restrict__ rois) {
    int n = threadIdx.x;
    if (n < NN) {
        float x1 = rois[4 * n + 0];
        float y1 = rois[4 * n + 1];
        float x2 = rois[4 * n + 2];
        float y2 = rois[4 * n + 3];
        float cw = fmaxf(x2 - x1, 1.0f);
        float ch = fmaxf(y2 - y1, 1.0f);
        // double-precision division so (x-x1)*sx tracks fp32 2*(x-x1)/cw to ~1-2 ulp
        float sx = (float)(2.0 / (double)cw);
        float sy = (float)(2.0 / (double)ch);
        g_prep[2 * n]     = make_float4(x1, y1, x2, y2);
        g_prep[2 * n + 1] = make_float4(sx, sy, 0.0f, 0.0f);
    }
}

__global__ void __launch_bounds__(256)
crop_split_kernel(const float* __restrict__ data, float* __restrict__ out) {
    int idx = blockIdx.x * 256 + threadIdx.x;
    if (idx >= TOTAL_THREADS) return;

    int n4 = idx % N4;          // group of 4 consecutive n
    int hw = idx / N4;          // h*WW + w
    int w  = hw % WW;
    int h  = hw / WW;

    float xf = (float)w;
    float yf = (float)h;
    int   base = hw * NN + n4 * 4;   // 16B aligned: NN and n4*4 are multiples of 4

    float v[4];

    #pragma unroll
    for (int i = 0; i < 4; i++) {
        int n = n4 * 4 + i;
        float4 r = g_prep[2 * n];       // x1,y1,x2,y2  (L1-resident table)
        float4 s = g_prep[2 * n + 1];   // sx,sy

        float val = 0.0f;
        bool inside = (xf >= r.x) & (xf <= r.z) & (yf >= r.y) & (yf <= r.w);
        if (inside) {
            int cx = (int)floorf((xf - r.x) * s.x);
            int cy = (int)floorf((yf - r.y) * s.y);
            cx = min(max(cx, 0), CC - 1);
            cy = min(max(cy, 0), CC - 1);
            int cell = cy * CC + cx;
            val = __ldg(data + (size_t)cell * HWN + base + i);
        }
        v[i] = val;
    }

    float4 o = make_float4(v[0], v[1], v[2], v[3]);
    *reinterpret_cast<float4*>(out + base) = o;
}

extern "C" void kernel_launch(void* const* d_in, const int* in_sizes, int n_in,
                              void* d_out, int out_size) {
    const float* data = (const float*)d_in[0];   // (4, H, W, N) fp32
    const float* rois = (const float*)d_in[1];   // (N, 4) fp32
    float* out = (float*)d_out;                  // (H, W, N) fp32

    prep_kernel<<<1, 256>>>(rois);

    int blocks = (TOTAL_THREADS + 255) / 256;    // 7813
    crop_split_kernel<<<blocks, 256>>>(data, out);
}

// round 2
// speedup vs baseline: 3.8011x; 3.8011x over previous
#include <cuda_runtime.h>

#define CC   2
#define HH   200
#define WW   200
#define NN   200
#define HWN  (HH*WW*NN)
#define N4   (NN/4)                     // 50 char4/float4 groups per (h,w)
#define TOTAL_THREADS (HH*WW*N4)        // 2,000,000

// Factorized per-axis cell tables (int8):
//   g_cx[w*NN + n] = cx in {0,1}, or -1 if x outside [x1,x2]
//   g_cy[h*NN + n] = cy in {0,1}, or -1 if y outside [y1,y2]
__device__ signed char g_cx[WW * NN];
__device__ signed char g_cy[HH * NN];

__global__ void prep_kernel(const float* __restrict__ rois) {
    int idx = blockIdx.x * blockDim.x + threadIdx.x;   // [0, 2*200*200)
    if (idx >= 2 * WW * NN) return;

    int axis = idx / (WW * NN);     // 0 = x, 1 = y
    int rem  = idx % (WW * NN);
    int p    = rem / NN;            // pixel coord (w or h)
    int n    = rem % NN;

    float lo = rois[4 * n + (axis ? 1 : 0)];   // x1 or y1
    float hi = rois[4 * n + (axis ? 3 : 2)];   // x2 or y2
    float cl = fmaxf(hi - lo, 1.0f);
    // double-precision reciprocal so (p-lo)*s tracks fp32 CC*(p-lo)/cl to ~1 ulp
    float s  = (float)((double)CC / (double)cl);

    float pf = (float)p;
    signed char v = -1;
    if (pf >= lo && pf <= hi) {
        int c = (int)floorf((pf - lo) * s);
        c = min(max(c, 0), CC - 1);
        v = (signed char)c;
    }
    if (axis == 0) g_cx[p * NN + n] = v;
    else           g_cy[p * NN + n] = v;
}

__global__ void __launch_bounds__(256)
crop_split_kernel(const float* __restrict__ data, float* __restrict__ out) {
    int idx = blockIdx.x * 256 + threadIdx.x;
    if (idx >= TOTAL_THREADS) return;

    int n4 = idx % N4;          // group of 4 consecutive n
    int hw = idx / N4;          // h*WW + w
    int w  = hw % WW;
    int h  = hw / WW;

    int base = hw * NN + n4 * 4;   // 16B aligned

    // 8 bytes of metadata per 16 bytes of output
    char4 cx4 = *reinterpret_cast<const char4*>(g_cx + w * NN + n4 * 4);
    char4 cy4 = *reinterpret_cast<const char4*>(g_cy + h * NN + n4 * 4);

    signed char cxs[4] = {cx4.x, cx4.y, cx4.z, cx4.w};
    signed char cys[4] = {cy4.x, cy4.y, cy4.z, cy4.w};

    float v[4];
    #pragma unroll
    for (int i = 0; i < 4; i++) {
        int cx = cxs[i];
        int cy = cys[i];
        float val = 0.0f;
        if ((cx | cy) >= 0) {
            int cell = cy * CC + cx;
            val = __ldg(data + (size_t)cell * HWN + base + i);
        }
        v[i] = val;
    }

    *reinterpret_cast<float4*>(out + base) = make_float4(v[0], v[1], v[2], v[3]);
}

extern "C" void kernel_launch(void* const* d_in, const int* in_sizes, int n_in,
                              void* d_out, int out_size) {
    const float* data = (const float*)d_in[0];   // (4, H, W, N) fp32
    const float* rois = (const float*)d_in[1];   // (N, 4) fp32
    float* out = (float*)d_out;                  // (H, W, N) fp32

    int prep_elems = 2 * WW * NN;                // 80000
    prep_kernel<<<(prep_elems + 255) / 256, 256>>>(rois);

    int blocks = (TOTAL_THREADS + 255) / 256;    // 7813
    crop_split_kernel<<<blocks, 256>>>(data, out);
}